// round 13
// baseline (speedup 1.0000x reference)
#include <cuda_runtime.h>
#include <cstdint>

#define NB 16
#define NS 196
#define NHEADS 8
#define NDH 64
#define NHID 512
#define NM (NB*NS)                       // 3136 rows for projections
#define BUF_ELEMS (NB*NHEADS*NS*NDH)     // 1,605,632 floats per buffer

__device__ float g_Q[BUF_ELEMS];
__device__ float g_K[BUF_ELEMS];
__device__ float g_V[BUF_ELEMS];
__device__ float g_G[BUF_ELEMS];

// ---- tf32 helpers ----
__device__ __forceinline__ float tf32_hi(float x) {
    return __uint_as_float(__float_as_uint(x) & 0xffffe000u);
}
__device__ __forceinline__ void mma_tf32(float* d, const uint32_t* a, const uint32_t* b) {
    asm volatile(
        "mma.sync.aligned.m16n8k8.row.col.f32.tf32.tf32.f32 "
        "{%0,%1,%2,%3}, {%4,%5,%6,%7}, {%8,%9}, {%0,%1,%2,%3};"
        : "+f"(d[0]), "+f"(d[1]), "+f"(d[2]), "+f"(d[3])
        : "r"(a[0]), "r"(a[1]), "r"(a[2]), "r"(a[3]), "r"(b[0]), "r"(b[1]));
}

// ---------------------------------------------------------------------------
// Kernel 1: fused QKVG projections via tf32 tensor-core MMA, 3xTF32 precision.
// (validated: rel_err ~8e-6; unchanged)
// ---------------------------------------------------------------------------
#define PP 136   // smem pitch (floats): 136 % 32 == 8 -> conflict-free fragments

__global__ __launch_bounds__(256) void proj_kernel(
    const float* __restrict__ X,
    const float* __restrict__ W0, const float* __restrict__ b0,
    const float* __restrict__ W1, const float* __restrict__ b1,
    const float* __restrict__ W2, const float* __restrict__ b2,
    const float* __restrict__ W3, const float* __restrict__ b3)
{
    const float* W;
    const float* bias;
    float* out;
    switch (blockIdx.z) {
        case 0:  W = W0; bias = b0; out = g_Q; break;
        case 1:  W = W1; bias = b1; out = g_K; break;
        case 2:  W = W2; bias = b2; out = g_V; break;
        default: W = W3; bias = b3; out = g_G; break;
    }

    __shared__ float As_hi[16][PP];
    __shared__ float As_lo[16][PP];
    __shared__ float Bs_hi[16][PP];
    __shared__ float Bs_lo[16][PP];

    const int m0 = blockIdx.y * 128;
    const int n0 = blockIdx.x * 128;
    const int tid  = threadIdx.x;
    const int warp = tid >> 5;
    const int lane = tid & 31;
    const int wm = (warp >> 2) * 64;
    const int wn = (warp & 3) * 32;

    float acc[4][4][4];
#pragma unroll
    for (int i = 0; i < 4; ++i)
#pragma unroll
        for (int j = 0; j < 4; ++j)
#pragma unroll
            for (int v = 0; v < 4; ++v) acc[i][j][v] = 0.f;

    for (int k0 = 0; k0 < NHID; k0 += 16) {
#pragma unroll
        for (int j = tid; j < 512; j += 256) {
            const int r  = j >> 2;
            const int c4 = (j & 3) * 4;
            float4 v = make_float4(0.f, 0.f, 0.f, 0.f);
            const int gm = m0 + r;
            if (gm < NM)
                v = *(const float4*)(X + (size_t)gm * NHID + k0 + c4);
            const float h0 = tf32_hi(v.x), h1 = tf32_hi(v.y),
                        h2 = tf32_hi(v.z), h3 = tf32_hi(v.w);
            As_hi[c4 + 0][r] = h0; As_lo[c4 + 0][r] = tf32_hi(v.x - h0);
            As_hi[c4 + 1][r] = h1; As_lo[c4 + 1][r] = tf32_hi(v.y - h1);
            As_hi[c4 + 2][r] = h2; As_lo[c4 + 2][r] = tf32_hi(v.z - h2);
            As_hi[c4 + 3][r] = h3; As_lo[c4 + 3][r] = tf32_hi(v.w - h3);
        }
#pragma unroll
        for (int j = tid; j < 512; j += 256) {
            const int r  = j >> 5;
            const int c4 = (j & 31) * 4;
            const float4 v = *(const float4*)(W + (size_t)(k0 + r) * NHID + n0 + c4);
            float4 hi, lo;
            hi.x = tf32_hi(v.x); lo.x = tf32_hi(v.x - hi.x);
            hi.y = tf32_hi(v.y); lo.y = tf32_hi(v.y - hi.y);
            hi.z = tf32_hi(v.z); lo.z = tf32_hi(v.z - hi.z);
            hi.w = tf32_hi(v.w); lo.w = tf32_hi(v.w - hi.w);
            *(float4*)&Bs_hi[r][c4] = hi;
            *(float4*)&Bs_lo[r][c4] = lo;
        }
        __syncthreads();

#pragma unroll
        for (int ks = 0; ks < 16; ks += 8) {
            const int ca = ks + (lane & 3);
            const int ra = wm + (lane >> 2);
            uint32_t ah[4][4], al[4][4];
#pragma unroll
            for (int mt = 0; mt < 4; ++mt) {
                const int r = ra + mt * 16;
                ah[mt][0] = __float_as_uint(As_hi[ca][r]);
                ah[mt][1] = __float_as_uint(As_hi[ca][r + 8]);
                ah[mt][2] = __float_as_uint(As_hi[ca + 4][r]);
                ah[mt][3] = __float_as_uint(As_hi[ca + 4][r + 8]);
                al[mt][0] = __float_as_uint(As_lo[ca][r]);
                al[mt][1] = __float_as_uint(As_lo[ca][r + 8]);
                al[mt][2] = __float_as_uint(As_lo[ca + 4][r]);
                al[mt][3] = __float_as_uint(As_lo[ca + 4][r + 8]);
            }
            const int rb = ks + (lane & 3);
            const int cb = wn + (lane >> 2);
            uint32_t bh[4][2], bl[4][2];
#pragma unroll
            for (int nt = 0; nt < 4; ++nt) {
                bh[nt][0] = __float_as_uint(Bs_hi[rb][cb + nt * 8]);
                bh[nt][1] = __float_as_uint(Bs_hi[rb + 4][cb + nt * 8]);
                bl[nt][0] = __float_as_uint(Bs_lo[rb][cb + nt * 8]);
                bl[nt][1] = __float_as_uint(Bs_lo[rb + 4][cb + nt * 8]);
            }
#pragma unroll
            for (int mt = 0; mt < 4; ++mt)
#pragma unroll
                for (int nt = 0; nt < 4; ++nt) {
                    mma_tf32(acc[mt][nt], ah[mt], bh[nt]);
                    mma_tf32(acc[mt][nt], al[mt], bh[nt]);
                    mma_tf32(acc[mt][nt], ah[mt], bl[nt]);
                }
        }
        __syncthreads();
    }

#pragma unroll
    for (int mt = 0; mt < 4; ++mt) {
#pragma unroll
        for (int nt = 0; nt < 4; ++nt) {
#pragma unroll
            for (int v = 0; v < 4; ++v) {
                const int row = wm + mt * 16 + (lane >> 2) + (v >> 1) * 8;
                const int col = wn + nt * 8 + 2 * (lane & 3) + (v & 1);
                const int m = m0 + row;
                if (m >= NM) continue;
                const int n = n0 + col;
                const int bI = m / NS;
                const int sI = m - bI * NS;
                const int h = n >> 6, d = n & 63;
                out[(((size_t)bI * NHEADS + h) * NS + sI) * NDH + d] =
                    acc[mt][nt][v] + bias[n];
            }
        }
    }
}

// ---------------------------------------------------------------------------
// Kernel 2: attention with geometric bias.
// Phase 1 is an async pipeline: each warp owns a private 3-slot SMEM ring;
// each task = 4 rpe rows (1KB) fetched with cp.async.cg (no register staging,
// L1 bypass), 2 stages always in flight, consumed via LDS.128.
// Ring row pitch 68 floats -> LDS at the 4-phase bank minimum.
// ---------------------------------------------------------------------------
#define TQ 14
#define SP 200
#define NG 49            // 196 / 4 k-groups
#define NTT (TQ * NG)    // 686 tasks per block
#define RPITCH 68        // ring row pitch in floats
#define SLOTF (4 * RPITCH)   // 272 floats per slot

__device__ __forceinline__ float dot4(float4 a, float4 b) {
    return a.x * b.x + a.y * b.y + a.z * b.z + a.w * b.w;
}

__global__ __launch_bounds__(256, 5) void attn_kernel(
    const float* __restrict__ rpe, const float* __restrict__ mask,
    float* __restrict__ out_ctx, float* __restrict__ out_probs,
    int write_probs)
{
    __shared__ __align__(16) float ring[8][3][SLOTF];  // 26112 B
    __shared__ float qsm[TQ * NDH];   // pre-scaled q
    __shared__ float gsm[TQ * NDH];
    __shared__ float sc[TQ * SP];
    __shared__ float msk[NS];

    const int q0 = blockIdx.x * TQ;
    const int h  = blockIdx.y;
    const int b  = blockIdx.z;
    const int bh = b * NHEADS + h;
    const int tid  = threadIdx.x;
    const int warp = tid >> 5;
    const int lane = tid & 31;
    const int kk  = lane >> 3;   // 0..3: k-row within 4-group
    const int sub = lane & 7;    // 0..7: 16B segment

    // ---- stage q, g, mask ----
    {
        const float* Qb = g_Q + ((size_t)bh * NS + q0) * NDH;
        const float* Gb = g_G + ((size_t)bh * NS + q0) * NDH;
        for (int j = tid; j < TQ * NDH; j += 256) {
            qsm[j] = Qb[j] * 0.125f;   // 1/sqrt(64)
            gsm[j] = Gb[j];
        }
        if (tid < NS) msk[tid] = mask[b * NS + tid];
    }
    __syncthreads();

    // ---- phase 0: sc = scale*q.K + mask (K rows read once, reused 14x) ----
    const float* Kbh = g_K + (size_t)bh * NS * NDH;
    for (int grp = warp; grp < NG; grp += 8) {
        const int k = grp * 4 + kk;          // always < 196
        const float* krow = Kbh + (size_t)k * NDH;
        const float4 kv0 = *(const float4*)(krow + sub * 4);
        const float4 kv1 = *(const float4*)(krow + (sub + 8) * 4);
        for (int qi = 0; qi < TQ; ++qi) {
            const float4 q0v = *(const float4*)&qsm[qi * NDH + sub * 4];
            const float4 q1v = *(const float4*)&qsm[qi * NDH + (sub + 8) * 4];
            float a = dot4(q0v, kv0) + dot4(q1v, kv1);
            a += __shfl_xor_sync(0xffffffffu, a, 1);
            a += __shfl_xor_sync(0xffffffffu, a, 2);
            a += __shfl_xor_sync(0xffffffffu, a, 4);
            if (sub == 0) sc[qi * SP + k] = a + msk[k];
        }
    }
    __syncthreads();

    // ---- phase 1: sc += g.rpe via cp.async pipeline ----
    const float* rb = rpe + ((size_t)bh * NS + q0) * (size_t)NS * NDH;

    // fetch lambda (task t -> ring[warp][slot]); 2 cp.async.cg 16B per lane
    auto fetch = [&](int t, int slot) {
        const int qi  = t / NG;
        const int grp = t - qi * NG;
        const float* srcb = rb + ((size_t)qi * NS + grp * 4) * NDH;
        float* dstb = &ring[warp][slot][0];
#pragma unroll
        for (int i = 0; i < 2; ++i) {
            const int chunk = i * 32 + lane;       // 0..63
            const int row = chunk >> 4;            // 0..3
            const int c   = chunk & 15;            // 16B chunk within row
            const float* src = srcb + row * NDH + c * 4;
            const uint32_t dst =
                (uint32_t)__cvta_generic_to_shared(dstb + row * RPITCH + c * 4);
            asm volatile("cp.async.cg.shared.global [%0], [%1], 16;\n"
                         :: "r"(dst), "l"(src));
        }
        asm volatile("cp.async.commit_group;\n" ::: "memory");
    };

    // prefill 2 stages
    int tf = warp;
    fetch(tf, 0); tf += 8;
    if (tf < NTT) { fetch(tf, 1); } else { asm volatile("cp.async.commit_group;\n" ::: "memory"); }
    tf += 8;

    int slot = 0;
    for (int tc = warp; tc < NTT; tc += 8) {
        asm volatile("cp.async.wait_group 1;\n" ::: "memory");
        __syncwarp();

        // consume current slot
        const int qi  = tc / NG;
        const int grp = tc - qi * NG;
        const int k   = grp * 4 + kk;
        const float* sl = &ring[warp][slot][0];
        const float4 r0 = *(const float4*)(sl + kk * RPITCH + sub * 4);
        const float4 r1 = *(const float4*)(sl + kk * RPITCH + 32 + sub * 4);
        const float4 g0 = *(const float4*)&gsm[qi * NDH + sub * 4];
        const float4 g1 = *(const float4*)&gsm[qi * NDH + 32 + sub * 4];
        float s = dot4(g0, r0) + dot4(g1, r1);
        s += __shfl_xor_sync(0xffffffffu, s, 1);
        s += __shfl_xor_sync(0xffffffffu, s, 2);
        s += __shfl_xor_sync(0xffffffffu, s, 4);
        if (sub == 0) sc[qi * SP + k] += s;

        // refill the slot consumed last iteration
        const int ns = (slot + 2 >= 3) ? slot - 1 : slot + 2;
        if (tf < NTT) { fetch(tf, ns); }
        else { asm volatile("cp.async.commit_group;\n" ::: "memory"); }
        tf += 8;
        slot = (slot + 1 == 3) ? 0 : slot + 1;
    }
    asm volatile("cp.async.wait_group 0;\n" ::: "memory");
    __syncthreads();

    // ---- phase 2: softmax per row + probs write ----
    for (int qi = warp; qi < TQ; qi += 8) {
        float m = -1e30f;
        for (int j = lane; j < NS; j += 32) m = fmaxf(m, sc[qi * SP + j]);
#pragma unroll
        for (int o = 16; o; o >>= 1) m = fmaxf(m, __shfl_xor_sync(0xffffffffu, m, o));
        float sum = 0.f;
        for (int j = lane; j < NS; j += 32) {
            const float e = __expf(sc[qi * SP + j] - m);
            sc[qi * SP + j] = e;
            sum += e;
        }
#pragma unroll
        for (int o = 16; o; o >>= 1) sum += __shfl_xor_sync(0xffffffffu, sum, o);
        const float inv = 1.0f / sum;
        const size_t pb = ((size_t)bh * NS + q0 + qi) * NS;
        for (int j = lane; j < NS; j += 32) {
            const float p = sc[qi * SP + j] * inv;
            sc[qi * SP + j] = p;
            if (write_probs) out_probs[pb + j] = p;
        }
    }
    __syncthreads();

    // ---- phase 3: ctx = probs @ V ----
    const int g = tid >> 6;      // 0..3
    const int d = tid & 63;
    const int nq = (g < 2) ? 4 : 3;
    const float* Vb = g_V + (size_t)bh * NS * NDH;

    float acc[4] = {0.f, 0.f, 0.f, 0.f};
#pragma unroll 4
    for (int k = 0; k < NS; ++k) {
        const float v = Vb[(size_t)k * NDH + d];
#pragma unroll
        for (int t = 0; t < 4; ++t)
            if (t < nq) acc[t] += sc[(g + 4 * t) * SP + k] * v;
    }
#pragma unroll
    for (int t = 0; t < 4; ++t) {
        if (t >= nq) break;
        const int qi = g + 4 * t;
        out_ctx[(((size_t)b * NS + q0 + qi) * NHEADS + h) * NDH + d] = acc[t];
    }
}

// ---------------------------------------------------------------------------
extern "C" void kernel_launch(void* const* d_in, const int* in_sizes, int n_in,
                              void* d_out, int out_size)
{
    const float* hidden = (const float*)d_in[0];
    const float* rpe    = (const float*)d_in[1];
    const float* mask   = (const float*)d_in[2];
    const float* Wq = (const float*)d_in[3];
    const float* bq = (const float*)d_in[4];
    const float* Wk = (const float*)d_in[5];
    const float* bk = (const float*)d_in[6];
    const float* Wv = (const float*)d_in[7];
    const float* bv = (const float*)d_in[8];
    const float* Wg = (const float*)d_in[9];
    const float* bg = (const float*)d_in[10];

    float* out = (float*)d_out;
    const size_t ctx_elems   = (size_t)NB * NS * NHID;
    const size_t probs_elems = (size_t)NB * NHEADS * NS * NS;
    const int write_probs = ((size_t)out_size >= ctx_elems + probs_elems) ? 1 : 0;
    float* out_probs = out + ctx_elems;

    proj_kernel<<<dim3(4, 25, 4), 256>>>(hidden, Wq, bq, Wk, bk, Wv, bv, Wg, bg);
    attn_kernel<<<dim3(NS / TQ, NHEADS, NB), 256>>>(
        rpe, mask, out, out_probs, write_probs);
}

// round 14
// speedup vs baseline: 1.0033x; 1.0033x over previous
#include <cuda_runtime.h>
#include <cstdint>

#define NB 16
#define NS 196
#define NHEADS 8
#define NDH 64
#define NHID 512
#define NM (NB*NS)                       // 3136 rows for projections
#define BUF_ELEMS (NB*NHEADS*NS*NDH)     // 1,605,632 floats per buffer

__device__ float g_Q[BUF_ELEMS];
__device__ float g_K[BUF_ELEMS];
__device__ float g_V[BUF_ELEMS];
__device__ float g_G[BUF_ELEMS];

// ---- tf32 helpers ----
__device__ __forceinline__ float tf32_hi(float x) {
    return __uint_as_float(__float_as_uint(x) & 0xffffe000u);
}
__device__ __forceinline__ void mma_tf32(float* d, const uint32_t* a, const uint32_t* b) {
    asm volatile(
        "mma.sync.aligned.m16n8k8.row.col.f32.tf32.tf32.f32 "
        "{%0,%1,%2,%3}, {%4,%5,%6,%7}, {%8,%9}, {%0,%1,%2,%3};"
        : "+f"(d[0]), "+f"(d[1]), "+f"(d[2]), "+f"(d[3])
        : "r"(a[0]), "r"(a[1]), "r"(a[2]), "r"(a[3]), "r"(b[0]), "r"(b[1]));
}

// ---------------------------------------------------------------------------
// Kernel 1: fused QKVG projections via tf32 tensor-core MMA, 3xTF32 precision.
// (validated: rel_err ~8e-6; unchanged)
// ---------------------------------------------------------------------------
#define PP 136   // smem pitch (floats): 136 % 32 == 8 -> conflict-free fragments

__global__ __launch_bounds__(256) void proj_kernel(
    const float* __restrict__ X,
    const float* __restrict__ W0, const float* __restrict__ b0,
    const float* __restrict__ W1, const float* __restrict__ b1,
    const float* __restrict__ W2, const float* __restrict__ b2,
    const float* __restrict__ W3, const float* __restrict__ b3)
{
    const float* W;
    const float* bias;
    float* out;
    switch (blockIdx.z) {
        case 0:  W = W0; bias = b0; out = g_Q; break;
        case 1:  W = W1; bias = b1; out = g_K; break;
        case 2:  W = W2; bias = b2; out = g_V; break;
        default: W = W3; bias = b3; out = g_G; break;
    }

    __shared__ float As_hi[16][PP];
    __shared__ float As_lo[16][PP];
    __shared__ float Bs_hi[16][PP];
    __shared__ float Bs_lo[16][PP];

    const int m0 = blockIdx.y * 128;
    const int n0 = blockIdx.x * 128;
    const int tid  = threadIdx.x;
    const int warp = tid >> 5;
    const int lane = tid & 31;
    const int wm = (warp >> 2) * 64;
    const int wn = (warp & 3) * 32;

    float acc[4][4][4];
#pragma unroll
    for (int i = 0; i < 4; ++i)
#pragma unroll
        for (int j = 0; j < 4; ++j)
#pragma unroll
            for (int v = 0; v < 4; ++v) acc[i][j][v] = 0.f;

    for (int k0 = 0; k0 < NHID; k0 += 16) {
#pragma unroll
        for (int j = tid; j < 512; j += 256) {
            const int r  = j >> 2;
            const int c4 = (j & 3) * 4;
            float4 v = make_float4(0.f, 0.f, 0.f, 0.f);
            const int gm = m0 + r;
            if (gm < NM)
                v = *(const float4*)(X + (size_t)gm * NHID + k0 + c4);
            const float h0 = tf32_hi(v.x), h1 = tf32_hi(v.y),
                        h2 = tf32_hi(v.z), h3 = tf32_hi(v.w);
            As_hi[c4 + 0][r] = h0; As_lo[c4 + 0][r] = tf32_hi(v.x - h0);
            As_hi[c4 + 1][r] = h1; As_lo[c4 + 1][r] = tf32_hi(v.y - h1);
            As_hi[c4 + 2][r] = h2; As_lo[c4 + 2][r] = tf32_hi(v.z - h2);
            As_hi[c4 + 3][r] = h3; As_lo[c4 + 3][r] = tf32_hi(v.w - h3);
        }
#pragma unroll
        for (int j = tid; j < 512; j += 256) {
            const int r  = j >> 5;
            const int c4 = (j & 31) * 4;
            const float4 v = *(const float4*)(W + (size_t)(k0 + r) * NHID + n0 + c4);
            float4 hi, lo;
            hi.x = tf32_hi(v.x); lo.x = tf32_hi(v.x - hi.x);
            hi.y = tf32_hi(v.y); lo.y = tf32_hi(v.y - hi.y);
            hi.z = tf32_hi(v.z); lo.z = tf32_hi(v.z - hi.z);
            hi.w = tf32_hi(v.w); lo.w = tf32_hi(v.w - hi.w);
            *(float4*)&Bs_hi[r][c4] = hi;
            *(float4*)&Bs_lo[r][c4] = lo;
        }
        __syncthreads();

#pragma unroll
        for (int ks = 0; ks < 16; ks += 8) {
            const int ca = ks + (lane & 3);
            const int ra = wm + (lane >> 2);
            uint32_t ah[4][4], al[4][4];
#pragma unroll
            for (int mt = 0; mt < 4; ++mt) {
                const int r = ra + mt * 16;
                ah[mt][0] = __float_as_uint(As_hi[ca][r]);
                ah[mt][1] = __float_as_uint(As_hi[ca][r + 8]);
                ah[mt][2] = __float_as_uint(As_hi[ca + 4][r]);
                ah[mt][3] = __float_as_uint(As_hi[ca + 4][r + 8]);
                al[mt][0] = __float_as_uint(As_lo[ca][r]);
                al[mt][1] = __float_as_uint(As_lo[ca][r + 8]);
                al[mt][2] = __float_as_uint(As_lo[ca + 4][r]);
                al[mt][3] = __float_as_uint(As_lo[ca + 4][r + 8]);
            }
            const int rb = ks + (lane & 3);
            const int cb = wn + (lane >> 2);
            uint32_t bh[4][2], bl[4][2];
#pragma unroll
            for (int nt = 0; nt < 4; ++nt) {
                bh[nt][0] = __float_as_uint(Bs_hi[rb][cb + nt * 8]);
                bh[nt][1] = __float_as_uint(Bs_hi[rb + 4][cb + nt * 8]);
                bl[nt][0] = __float_as_uint(Bs_lo[rb][cb + nt * 8]);
                bl[nt][1] = __float_as_uint(Bs_lo[rb + 4][cb + nt * 8]);
            }
#pragma unroll
            for (int mt = 0; mt < 4; ++mt)
#pragma unroll
                for (int nt = 0; nt < 4; ++nt) {
                    mma_tf32(acc[mt][nt], ah[mt], bh[nt]);
                    mma_tf32(acc[mt][nt], al[mt], bh[nt]);
                    mma_tf32(acc[mt][nt], ah[mt], bl[nt]);
                }
        }
        __syncthreads();
    }

#pragma unroll
    for (int mt = 0; mt < 4; ++mt) {
#pragma unroll
        for (int nt = 0; nt < 4; ++nt) {
#pragma unroll
            for (int v = 0; v < 4; ++v) {
                const int row = wm + mt * 16 + (lane >> 2) + (v >> 1) * 8;
                const int col = wn + nt * 8 + 2 * (lane & 3) + (v & 1);
                const int m = m0 + row;
                if (m >= NM) continue;
                const int n = n0 + col;
                const int bI = m / NS;
                const int sI = m - bI * NS;
                const int h = n >> 6, d = n & 63;
                out[(((size_t)bI * NHEADS + h) * NS + sI) * NDH + d] =
                    acc[mt][nt][v] + bias[n];
            }
        }
    }
}

// ---------------------------------------------------------------------------
// Kernel 2: attention with geometric bias.
// Phase 1: qi-outer rpe stream with NO shuffle reduction: each lane writes its
// 8-element partial dot to a pitch-9 SMEM buffer (1 STS), then a 196-thread
// reduce pass sums 8 partials per k into sc. Per task: 8 LDG.128 + 16 FMA +
// 1 STS — no serial shuffle tail, no division.
// ---------------------------------------------------------------------------
#define TQ 14
#define SP 200
#define NG 49            // 196 / 4 k-groups
#define PPIT 9           // partial-buffer pitch (9 coprime 32 -> conflict-free)

__device__ __forceinline__ float dot4(float4 a, float4 b) {
    return a.x * b.x + a.y * b.y + a.z * b.z + a.w * b.w;
}

__global__ __launch_bounds__(256, 5) void attn_kernel(
    const float* __restrict__ rpe, const float* __restrict__ mask,
    float* __restrict__ out_ctx, float* __restrict__ out_probs,
    int write_probs)
{
    __shared__ float part[NS * PPIT];  // 7056 B partial dots
    __shared__ float qsm[TQ * NDH];    // pre-scaled q
    __shared__ float gsm[TQ * NDH];
    __shared__ float sc[TQ * SP];
    __shared__ float msk[NS];

    const int q0 = blockIdx.x * TQ;
    const int h  = blockIdx.y;
    const int b  = blockIdx.z;
    const int bh = b * NHEADS + h;
    const int tid  = threadIdx.x;
    const int warp = tid >> 5;
    const int lane = tid & 31;
    const int kk  = lane >> 3;   // 0..3: k-row within 4-group
    const int sub = lane & 7;    // 0..7: 16B segment within row

    // ---- stage q, g, mask ----
    {
        const float* Qb = g_Q + ((size_t)bh * NS + q0) * NDH;
        const float* Gb = g_G + ((size_t)bh * NS + q0) * NDH;
        for (int j = tid; j < TQ * NDH; j += 256) {
            qsm[j] = Qb[j] * 0.125f;   // 1/sqrt(64)
            gsm[j] = Gb[j];
        }
        if (tid < NS) msk[tid] = mask[b * NS + tid];
    }
    __syncthreads();

    // ---- phase 0: sc = scale*q.K + mask (K rows read once, reused 14x) ----
    const float* Kbh = g_K + (size_t)bh * NS * NDH;
    for (int grp = warp; grp < NG; grp += 8) {
        const int k = grp * 4 + kk;          // always < 196
        const float* krow = Kbh + (size_t)k * NDH;
        const float4 kv0 = *(const float4*)(krow + sub * 4);
        const float4 kv1 = *(const float4*)(krow + (sub + 8) * 4);
        for (int qi = 0; qi < TQ; ++qi) {
            const float4 q0v = *(const float4*)&qsm[qi * NDH + sub * 4];
            const float4 q1v = *(const float4*)&qsm[qi * NDH + (sub + 8) * 4];
            float a = dot4(q0v, kv0) + dot4(q1v, kv1);
            a += __shfl_xor_sync(0xffffffffu, a, 1);
            a += __shfl_xor_sync(0xffffffffu, a, 2);
            a += __shfl_xor_sync(0xffffffffu, a, 4);
            if (sub == 0) sc[qi * SP + k] = a + msk[k];
        }
    }
    __syncthreads();

    // ---- phase 1: sc += g.rpe via SMEM partial sums (no shuffles) ----
    const float* rb = rpe + ((size_t)bh * NS + q0) * (size_t)NS * NDH;
    for (int qi = 0; qi < TQ; ++qi) {
        const float4 g0 = *(const float4*)&gsm[qi * NDH + sub * 4];
        const float4 g1 = *(const float4*)&gsm[qi * NDH + (sub + 8) * 4];
        const float* rq = rb + (size_t)qi * NS * NDH;

        // groups 0..47 round-robined over warps; group 48 rotates by qi
        for (int grp = warp; grp < 48; grp += 8) {
            const int k = grp * 4 + kk;
            const float* p = rq + (size_t)k * NDH;
            const float4 r0 = *(const float4*)(p + sub * 4);
            const float4 r1 = *(const float4*)(p + (sub + 8) * 4);
            part[k * PPIT + sub] = dot4(g0, r0) + dot4(g1, r1);
        }
        if (warp == (qi & 7)) {
            const int k = 192 + kk;
            const float* p = rq + (size_t)k * NDH;
            const float4 r0 = *(const float4*)(p + sub * 4);
            const float4 r1 = *(const float4*)(p + (sub + 8) * 4);
            part[k * PPIT + sub] = dot4(g0, r0) + dot4(g1, r1);
        }
        __syncthreads();

        // reduce 8 partials per k (pitch 9 -> conflict-free scalar LDS)
        if (tid < NS) {
            const float* pr = &part[tid * PPIT];
            float s = ((pr[0] + pr[1]) + (pr[2] + pr[3]))
                    + ((pr[4] + pr[5]) + (pr[6] + pr[7]));
            sc[qi * SP + tid] += s;
        }
        __syncthreads();
    }

    // ---- phase 2: softmax per row + probs write ----
    for (int qi = warp; qi < TQ; qi += 8) {
        float m = -1e30f;
        for (int j = lane; j < NS; j += 32) m = fmaxf(m, sc[qi * SP + j]);
#pragma unroll
        for (int o = 16; o; o >>= 1) m = fmaxf(m, __shfl_xor_sync(0xffffffffu, m, o));
        float sum = 0.f;
        for (int j = lane; j < NS; j += 32) {
            const float e = __expf(sc[qi * SP + j] - m);
            sc[qi * SP + j] = e;
            sum += e;
        }
#pragma unroll
        for (int o = 16; o; o >>= 1) sum += __shfl_xor_sync(0xffffffffu, sum, o);
        const float inv = 1.0f / sum;
        const size_t pb = ((size_t)bh * NS + q0 + qi) * NS;
        for (int j = lane; j < NS; j += 32) {
            const float p = sc[qi * SP + j] * inv;
            sc[qi * SP + j] = p;
            if (write_probs) out_probs[pb + j] = p;
        }
    }
    __syncthreads();

    // ---- phase 3: ctx = probs @ V ----
    const int g = tid >> 6;      // 0..3
    const int d = tid & 63;
    const int nq = (g < 2) ? 4 : 3;
    const float* Vb = g_V + (size_t)bh * NS * NDH;

    float acc[4] = {0.f, 0.f, 0.f, 0.f};
#pragma unroll 4
    for (int k = 0; k < NS; ++k) {
        const float v = Vb[(size_t)k * NDH + d];
#pragma unroll
        for (int t = 0; t < 4; ++t)
            if (t < nq) acc[t] += sc[(g + 4 * t) * SP + k] * v;
    }
#pragma unroll
    for (int t = 0; t < 4; ++t) {
        if (t >= nq) break;
        const int qi = g + 4 * t;
        out_ctx[(((size_t)b * NS + q0 + qi) * NHEADS + h) * NDH + d] = acc[t];
    }
}

// ---------------------------------------------------------------------------
extern "C" void kernel_launch(void* const* d_in, const int* in_sizes, int n_in,
                              void* d_out, int out_size)
{
    const float* hidden = (const float*)d_in[0];
    const float* rpe    = (const float*)d_in[1];
    const float* mask   = (const float*)d_in[2];
    const float* Wq = (const float*)d_in[3];
    const float* bq = (const float*)d_in[4];
    const float* Wk = (const float*)d_in[5];
    const float* bk = (const float*)d_in[6];
    const float* Wv = (const float*)d_in[7];
    const float* bv = (const float*)d_in[8];
    const float* Wg = (const float*)d_in[9];
    const float* bg = (const float*)d_in[10];

    float* out = (float*)d_out;
    const size_t ctx_elems   = (size_t)NB * NS * NHID;
    const size_t probs_elems = (size_t)NB * NHEADS * NS * NS;
    const int write_probs = ((size_t)out_size >= ctx_elems + probs_elems) ? 1 : 0;
    float* out_probs = out + ctx_elems;

    proj_kernel<<<dim3(4, 25, 4), 256>>>(hidden, Wq, bq, Wk, bk, Wv, bv, Wg, bg);
    attn_kernel<<<dim3(NS / TQ, NHEADS, NB), 256>>>(
        rpe, mask, out, out_probs, write_probs);
}

// round 15
// speedup vs baseline: 1.1222x; 1.1186x over previous
#include <cuda_runtime.h>
#include <cstdint>

#define NB 16
#define NS 196
#define NHEADS 8
#define NDH 64
#define NHID 512
#define NM (NB*NS)                       // 3136 rows for projections
#define BUF_ELEMS (NB*NHEADS*NS*NDH)     // 1,605,632 floats per buffer

__device__ float g_Q[BUF_ELEMS];
__device__ float g_K[BUF_ELEMS];
__device__ float g_V[BUF_ELEMS];
__device__ float g_G[BUF_ELEMS];

// ---- tf32 helpers ----
__device__ __forceinline__ float tf32_hi(float x) {
    return __uint_as_float(__float_as_uint(x) & 0xffffe000u);
}
__device__ __forceinline__ void mma_tf32(float* d, const uint32_t* a, const uint32_t* b) {
    asm volatile(
        "mma.sync.aligned.m16n8k8.row.col.f32.tf32.tf32.f32 "
        "{%0,%1,%2,%3}, {%4,%5,%6,%7}, {%8,%9}, {%0,%1,%2,%3};"
        : "+f"(d[0]), "+f"(d[1]), "+f"(d[2]), "+f"(d[3])
        : "r"(a[0]), "r"(a[1]), "r"(a[2]), "r"(a[3]), "r"(b[0]), "r"(b[1]));
}

// ---------------------------------------------------------------------------
// Kernel 1: fused QKVG projections via tf32 tensor-core MMA, 3xTF32 precision.
// (validated: rel_err ~8e-6; unchanged)
// ---------------------------------------------------------------------------
#define PP 136   // smem pitch (floats): 136 % 32 == 8 -> conflict-free fragments

__global__ __launch_bounds__(256) void proj_kernel(
    const float* __restrict__ X,
    const float* __restrict__ W0, const float* __restrict__ b0,
    const float* __restrict__ W1, const float* __restrict__ b1,
    const float* __restrict__ W2, const float* __restrict__ b2,
    const float* __restrict__ W3, const float* __restrict__ b3)
{
    const float* W;
    const float* bias;
    float* out;
    switch (blockIdx.z) {
        case 0:  W = W0; bias = b0; out = g_Q; break;
        case 1:  W = W1; bias = b1; out = g_K; break;
        case 2:  W = W2; bias = b2; out = g_V; break;
        default: W = W3; bias = b3; out = g_G; break;
    }

    __shared__ float As_hi[16][PP];
    __shared__ float As_lo[16][PP];
    __shared__ float Bs_hi[16][PP];
    __shared__ float Bs_lo[16][PP];

    const int m0 = blockIdx.y * 128;
    const int n0 = blockIdx.x * 128;
    const int tid  = threadIdx.x;
    const int warp = tid >> 5;
    const int lane = tid & 31;
    const int wm = (warp >> 2) * 64;
    const int wn = (warp & 3) * 32;

    float acc[4][4][4];
#pragma unroll
    for (int i = 0; i < 4; ++i)
#pragma unroll
        for (int j = 0; j < 4; ++j)
#pragma unroll
            for (int v = 0; v < 4; ++v) acc[i][j][v] = 0.f;

    for (int k0 = 0; k0 < NHID; k0 += 16) {
#pragma unroll
        for (int j = tid; j < 512; j += 256) {
            const int r  = j >> 2;
            const int c4 = (j & 3) * 4;
            float4 v = make_float4(0.f, 0.f, 0.f, 0.f);
            const int gm = m0 + r;
            if (gm < NM)
                v = *(const float4*)(X + (size_t)gm * NHID + k0 + c4);
            const float h0 = tf32_hi(v.x), h1 = tf32_hi(v.y),
                        h2 = tf32_hi(v.z), h3 = tf32_hi(v.w);
            As_hi[c4 + 0][r] = h0; As_lo[c4 + 0][r] = tf32_hi(v.x - h0);
            As_hi[c4 + 1][r] = h1; As_lo[c4 + 1][r] = tf32_hi(v.y - h1);
            As_hi[c4 + 2][r] = h2; As_lo[c4 + 2][r] = tf32_hi(v.z - h2);
            As_hi[c4 + 3][r] = h3; As_lo[c4 + 3][r] = tf32_hi(v.w - h3);
        }
#pragma unroll
        for (int j = tid; j < 512; j += 256) {
            const int r  = j >> 5;
            const int c4 = (j & 31) * 4;
            const float4 v = *(const float4*)(W + (size_t)(k0 + r) * NHID + n0 + c4);
            float4 hi, lo;
            hi.x = tf32_hi(v.x); lo.x = tf32_hi(v.x - hi.x);
            hi.y = tf32_hi(v.y); lo.y = tf32_hi(v.y - hi.y);
            hi.z = tf32_hi(v.z); lo.z = tf32_hi(v.z - hi.z);
            hi.w = tf32_hi(v.w); lo.w = tf32_hi(v.w - hi.w);
            *(float4*)&Bs_hi[r][c4] = hi;
            *(float4*)&Bs_lo[r][c4] = lo;
        }
        __syncthreads();

#pragma unroll
        for (int ks = 0; ks < 16; ks += 8) {
            const int ca = ks + (lane & 3);
            const int ra = wm + (lane >> 2);
            uint32_t ah[4][4], al[4][4];
#pragma unroll
            for (int mt = 0; mt < 4; ++mt) {
                const int r = ra + mt * 16;
                ah[mt][0] = __float_as_uint(As_hi[ca][r]);
                ah[mt][1] = __float_as_uint(As_hi[ca][r + 8]);
                ah[mt][2] = __float_as_uint(As_hi[ca + 4][r]);
                ah[mt][3] = __float_as_uint(As_hi[ca + 4][r + 8]);
                al[mt][0] = __float_as_uint(As_lo[ca][r]);
                al[mt][1] = __float_as_uint(As_lo[ca][r + 8]);
                al[mt][2] = __float_as_uint(As_lo[ca + 4][r]);
                al[mt][3] = __float_as_uint(As_lo[ca + 4][r + 8]);
            }
            const int rb = ks + (lane & 3);
            const int cb = wn + (lane >> 2);
            uint32_t bh[4][2], bl[4][2];
#pragma unroll
            for (int nt = 0; nt < 4; ++nt) {
                bh[nt][0] = __float_as_uint(Bs_hi[rb][cb + nt * 8]);
                bh[nt][1] = __float_as_uint(Bs_hi[rb + 4][cb + nt * 8]);
                bl[nt][0] = __float_as_uint(Bs_lo[rb][cb + nt * 8]);
                bl[nt][1] = __float_as_uint(Bs_lo[rb + 4][cb + nt * 8]);
            }
#pragma unroll
            for (int mt = 0; mt < 4; ++mt)
#pragma unroll
                for (int nt = 0; nt < 4; ++nt) {
                    mma_tf32(acc[mt][nt], ah[mt], bh[nt]);
                    mma_tf32(acc[mt][nt], al[mt], bh[nt]);
                    mma_tf32(acc[mt][nt], ah[mt], bl[nt]);
                }
        }
        __syncthreads();
    }

#pragma unroll
    for (int mt = 0; mt < 4; ++mt) {
#pragma unroll
        for (int nt = 0; nt < 4; ++nt) {
#pragma unroll
            for (int v = 0; v < 4; ++v) {
                const int row = wm + mt * 16 + (lane >> 2) + (v >> 1) * 8;
                const int col = wn + nt * 8 + 2 * (lane & 3) + (v & 1);
                const int m = m0 + row;
                if (m >= NM) continue;
                const int n = n0 + col;
                const int bI = m / NS;
                const int sI = m - bI * NS;
                const int h = n >> 6, d = n & 63;
                out[(((size_t)bI * NHEADS + h) * NS + sI) * NDH + d] =
                    acc[mt][nt][v] + bias[n];
            }
        }
    }
}

// ---------------------------------------------------------------------------
// Kernel 2: attention with geometric bias — FUSED score pass (R2 + R11 hybrid).
// k-group-outer: warp owns 4 k's (kk=lane>>3, sub=lane&7, full-128B lines).
// K row loaded ONCE into registers, reused for all 14 queries.
// qi-inner unrolled x2 with 4 rpe LDG.128 front-batched (R11 duty-cycle fix).
// One shuffle chain covers q.K + g.rpe + mask -> single STS to sc (no RMW).
// Group 48 falls naturally on warp 0 (48 % 8 == 0).
// ---------------------------------------------------------------------------
#define TQ 14
#define SP 200
#define NG 49            // 196 / 4 k-groups

__device__ __forceinline__ float dot4(float4 a, float4 b) {
    return a.x * b.x + a.y * b.y + a.z * b.z + a.w * b.w;
}

__global__ __launch_bounds__(256, 5) void attn_kernel(
    const float* __restrict__ rpe, const float* __restrict__ mask,
    float* __restrict__ out_ctx, float* __restrict__ out_probs,
    int write_probs)
{
    __shared__ float qsm[TQ * NDH];    // pre-scaled q
    __shared__ float gsm[TQ * NDH];
    __shared__ float sc[TQ * SP];
    __shared__ float msk[NS];

    const int q0 = blockIdx.x * TQ;
    const int h  = blockIdx.y;
    const int b  = blockIdx.z;
    const int bh = b * NHEADS + h;
    const int tid  = threadIdx.x;
    const int warp = tid >> 5;
    const int lane = tid & 31;
    const int kk  = lane >> 3;   // 0..3: k-row within 4-group
    const int sub = lane & 7;    // 0..7: 16B segment within row

    // ---- stage q, g, mask ----
    {
        const float* Qb = g_Q + ((size_t)bh * NS + q0) * NDH;
        const float* Gb = g_G + ((size_t)bh * NS + q0) * NDH;
        for (int j = tid; j < TQ * NDH; j += 256) {
            qsm[j] = Qb[j] * 0.125f;   // 1/sqrt(64)
            gsm[j] = Gb[j];
        }
        if (tid < NS) msk[tid] = mask[b * NS + tid];
    }
    __syncthreads();

    // ---- fused score pass: sc = scale*q.K + g.rpe + mask ----
    const float* Kbh = g_K + (size_t)bh * NS * NDH;
    const float* rb  = rpe + ((size_t)bh * NS + q0) * (size_t)NS * NDH;

    for (int grp = warp; grp < NG; grp += 8) {
        const int k = grp * 4 + kk;          // < 196 always
        const float* krow = Kbh + (size_t)k * NDH;
        const float4 kv0 = *(const float4*)(krow + sub * 4);
        const float4 kv1 = *(const float4*)(krow + (sub + 8) * 4);
        const float mk = msk[k];
        const float* rk = rb + (size_t)k * NDH;

#pragma unroll 2
        for (int qi = 0; qi < TQ; qi += 2) {
            const float* p0 = rk + (size_t)qi * NS * NDH;
            const float* p1 = p0 + (size_t)NS * NDH;
            // 4 rpe LDG.128, front-batched
            const float4 ra0 = *(const float4*)(p0 + sub * 4);
            const float4 ra1 = *(const float4*)(p0 + (sub + 8) * 4);
            const float4 rb0 = *(const float4*)(p1 + sub * 4);
            const float4 rb1 = *(const float4*)(p1 + (sub + 8) * 4);

            const float4 qa0 = *(const float4*)&qsm[qi * NDH + sub * 4];
            const float4 qa1 = *(const float4*)&qsm[qi * NDH + (sub + 8) * 4];
            const float4 ga0 = *(const float4*)&gsm[qi * NDH + sub * 4];
            const float4 ga1 = *(const float4*)&gsm[qi * NDH + (sub + 8) * 4];
            const float4 qb0 = *(const float4*)&qsm[(qi + 1) * NDH + sub * 4];
            const float4 qb1 = *(const float4*)&qsm[(qi + 1) * NDH + (sub + 8) * 4];
            const float4 gb0 = *(const float4*)&gsm[(qi + 1) * NDH + sub * 4];
            const float4 gb1 = *(const float4*)&gsm[(qi + 1) * NDH + (sub + 8) * 4];

            float sA = dot4(qa0, kv0) + dot4(qa1, kv1)
                     + dot4(ga0, ra0) + dot4(ga1, ra1);
            float sB = dot4(qb0, kv0) + dot4(qb1, kv1)
                     + dot4(gb0, rb0) + dot4(gb1, rb1);

            sA += __shfl_xor_sync(0xffffffffu, sA, 1);
            sB += __shfl_xor_sync(0xffffffffu, sB, 1);
            sA += __shfl_xor_sync(0xffffffffu, sA, 2);
            sB += __shfl_xor_sync(0xffffffffu, sB, 2);
            sA += __shfl_xor_sync(0xffffffffu, sA, 4);
            sB += __shfl_xor_sync(0xffffffffu, sB, 4);
            if (sub == 0) {
                sc[qi * SP + k]       = sA + mk;
                sc[(qi + 1) * SP + k] = sB + mk;
            }
        }
    }
    __syncthreads();

    // ---- softmax per row + probs write ----
    for (int qi = warp; qi < TQ; qi += 8) {
        float m = -1e30f;
        for (int j = lane; j < NS; j += 32) m = fmaxf(m, sc[qi * SP + j]);
#pragma unroll
        for (int o = 16; o; o >>= 1) m = fmaxf(m, __shfl_xor_sync(0xffffffffu, m, o));
        float sum = 0.f;
        for (int j = lane; j < NS; j += 32) {
            const float e = __expf(sc[qi * SP + j] - m);
            sc[qi * SP + j] = e;
            sum += e;
        }
#pragma unroll
        for (int o = 16; o; o >>= 1) sum += __shfl_xor_sync(0xffffffffu, sum, o);
        const float inv = 1.0f / sum;
        const size_t pb = ((size_t)bh * NS + q0 + qi) * NS;
        for (int j = lane; j < NS; j += 32) {
            const float p = sc[qi * SP + j] * inv;
            sc[qi * SP + j] = p;
            if (write_probs) out_probs[pb + j] = p;
        }
    }
    __syncthreads();

    // ---- ctx = probs @ V ----
    const int g = tid >> 6;      // 0..3
    const int d = tid & 63;
    const int nq = (g < 2) ? 4 : 3;
    const float* Vb = g_V + (size_t)bh * NS * NDH;

    float acc[4] = {0.f, 0.f, 0.f, 0.f};
#pragma unroll 4
    for (int k = 0; k < NS; ++k) {
        const float v = Vb[(size_t)k * NDH + d];
#pragma unroll
        for (int t = 0; t < 4; ++t)
            if (t < nq) acc[t] += sc[(g + 4 * t) * SP + k] * v;
    }
#pragma unroll
    for (int t = 0; t < 4; ++t) {
        if (t >= nq) break;
        const int qi = g + 4 * t;
        out_ctx[(((size_t)b * NS + q0 + qi) * NHEADS + h) * NDH + d] = acc[t];
    }
}

// ---------------------------------------------------------------------------
extern "C" void kernel_launch(void* const* d_in, const int* in_sizes, int n_in,
                              void* d_out, int out_size)
{
    const float* hidden = (const float*)d_in[0];
    const float* rpe    = (const float*)d_in[1];
    const float* mask   = (const float*)d_in[2];
    const float* Wq = (const float*)d_in[3];
    const float* bq = (const float*)d_in[4];
    const float* Wk = (const float*)d_in[5];
    const float* bk = (const float*)d_in[6];
    const float* Wv = (const float*)d_in[7];
    const float* bv = (const float*)d_in[8];
    const float* Wg = (const float*)d_in[9];
    const float* bg = (const float*)d_in[10];

    float* out = (float*)d_out;
    const size_t ctx_elems   = (size_t)NB * NS * NHID;
    const size_t probs_elems = (size_t)NB * NHEADS * NS * NS;
    const int write_probs = ((size_t)out_size >= ctx_elems + probs_elems) ? 1 : 0;
    float* out_probs = out + ctx_elems;

    proj_kernel<<<dim3(4, 25, 4), 256>>>(hidden, Wq, bq, Wk, bk, Wv, bv, Wg, bg);
    attn_kernel<<<dim3(NS / TQ, NHEADS, NB), 256>>>(
        rpe, mask, out, out_probs, write_probs);
}

// round 16
// speedup vs baseline: 1.1357x; 1.0120x over previous
#include <cuda_runtime.h>
#include <cstdint>

#define NB 16
#define NS 196
#define NHEADS 8
#define NDH 64
#define NHID 512
#define NM (NB*NS)                       // 3136 rows for projections
#define BUF_ELEMS (NB*NHEADS*NS*NDH)     // 1,605,632 floats per buffer

__device__ float g_Q[BUF_ELEMS];
__device__ float g_K[BUF_ELEMS];
__device__ float g_V[BUF_ELEMS];
__device__ float g_G[BUF_ELEMS];

// ---- tf32 helpers ----
__device__ __forceinline__ float tf32_hi(float x) {
    return __uint_as_float(__float_as_uint(x) & 0xffffe000u);
}
__device__ __forceinline__ void mma_tf32(float* d, const uint32_t* a, const uint32_t* b) {
    asm volatile(
        "mma.sync.aligned.m16n8k8.row.col.f32.tf32.tf32.f32 "
        "{%0,%1,%2,%3}, {%4,%5,%6,%7}, {%8,%9}, {%0,%1,%2,%3};"
        : "+f"(d[0]), "+f"(d[1]), "+f"(d[2]), "+f"(d[3])
        : "r"(a[0]), "r"(a[1]), "r"(a[2]), "r"(a[3]), "r"(b[0]), "r"(b[1]));
}

// ---------------------------------------------------------------------------
// Kernel 1: fused QKVG projections via tf32 tensor-core MMA, 3xTF32 precision.
// (validated: rel_err ~8e-6; unchanged)
// ---------------------------------------------------------------------------
#define PP 136   // smem pitch (floats): 136 % 32 == 8 -> conflict-free fragments

__global__ __launch_bounds__(256) void proj_kernel(
    const float* __restrict__ X,
    const float* __restrict__ W0, const float* __restrict__ b0,
    const float* __restrict__ W1, const float* __restrict__ b1,
    const float* __restrict__ W2, const float* __restrict__ b2,
    const float* __restrict__ W3, const float* __restrict__ b3)
{
    const float* W;
    const float* bias;
    float* out;
    switch (blockIdx.z) {
        case 0:  W = W0; bias = b0; out = g_Q; break;
        case 1:  W = W1; bias = b1; out = g_K; break;
        case 2:  W = W2; bias = b2; out = g_V; break;
        default: W = W3; bias = b3; out = g_G; break;
    }

    __shared__ float As_hi[16][PP];
    __shared__ float As_lo[16][PP];
    __shared__ float Bs_hi[16][PP];
    __shared__ float Bs_lo[16][PP];

    const int m0 = blockIdx.y * 128;
    const int n0 = blockIdx.x * 128;
    const int tid  = threadIdx.x;
    const int warp = tid >> 5;
    const int lane = tid & 31;
    const int wm = (warp >> 2) * 64;
    const int wn = (warp & 3) * 32;

    float acc[4][4][4];
#pragma unroll
    for (int i = 0; i < 4; ++i)
#pragma unroll
        for (int j = 0; j < 4; ++j)
#pragma unroll
            for (int v = 0; v < 4; ++v) acc[i][j][v] = 0.f;

    for (int k0 = 0; k0 < NHID; k0 += 16) {
#pragma unroll
        for (int j = tid; j < 512; j += 256) {
            const int r  = j >> 2;
            const int c4 = (j & 3) * 4;
            float4 v = make_float4(0.f, 0.f, 0.f, 0.f);
            const int gm = m0 + r;
            if (gm < NM)
                v = *(const float4*)(X + (size_t)gm * NHID + k0 + c4);
            const float h0 = tf32_hi(v.x), h1 = tf32_hi(v.y),
                        h2 = tf32_hi(v.z), h3 = tf32_hi(v.w);
            As_hi[c4 + 0][r] = h0; As_lo[c4 + 0][r] = tf32_hi(v.x - h0);
            As_hi[c4 + 1][r] = h1; As_lo[c4 + 1][r] = tf32_hi(v.y - h1);
            As_hi[c4 + 2][r] = h2; As_lo[c4 + 2][r] = tf32_hi(v.z - h2);
            As_hi[c4 + 3][r] = h3; As_lo[c4 + 3][r] = tf32_hi(v.w - h3);
        }
#pragma unroll
        for (int j = tid; j < 512; j += 256) {
            const int r  = j >> 5;
            const int c4 = (j & 31) * 4;
            const float4 v = *(const float4*)(W + (size_t)(k0 + r) * NHID + n0 + c4);
            float4 hi, lo;
            hi.x = tf32_hi(v.x); lo.x = tf32_hi(v.x - hi.x);
            hi.y = tf32_hi(v.y); lo.y = tf32_hi(v.y - hi.y);
            hi.z = tf32_hi(v.z); lo.z = tf32_hi(v.z - hi.z);
            hi.w = tf32_hi(v.w); lo.w = tf32_hi(v.w - hi.w);
            *(float4*)&Bs_hi[r][c4] = hi;
            *(float4*)&Bs_lo[r][c4] = lo;
        }
        __syncthreads();

#pragma unroll
        for (int ks = 0; ks < 16; ks += 8) {
            const int ca = ks + (lane & 3);
            const int ra = wm + (lane >> 2);
            uint32_t ah[4][4], al[4][4];
#pragma unroll
            for (int mt = 0; mt < 4; ++mt) {
                const int r = ra + mt * 16;
                ah[mt][0] = __float_as_uint(As_hi[ca][r]);
                ah[mt][1] = __float_as_uint(As_hi[ca][r + 8]);
                ah[mt][2] = __float_as_uint(As_hi[ca + 4][r]);
                ah[mt][3] = __float_as_uint(As_hi[ca + 4][r + 8]);
                al[mt][0] = __float_as_uint(As_lo[ca][r]);
                al[mt][1] = __float_as_uint(As_lo[ca][r + 8]);
                al[mt][2] = __float_as_uint(As_lo[ca + 4][r]);
                al[mt][3] = __float_as_uint(As_lo[ca + 4][r + 8]);
            }
            const int rb = ks + (lane & 3);
            const int cb = wn + (lane >> 2);
            uint32_t bh[4][2], bl[4][2];
#pragma unroll
            for (int nt = 0; nt < 4; ++nt) {
                bh[nt][0] = __float_as_uint(Bs_hi[rb][cb + nt * 8]);
                bh[nt][1] = __float_as_uint(Bs_hi[rb + 4][cb + nt * 8]);
                bl[nt][0] = __float_as_uint(Bs_lo[rb][cb + nt * 8]);
                bl[nt][1] = __float_as_uint(Bs_lo[rb + 4][cb + nt * 8]);
            }
#pragma unroll
            for (int mt = 0; mt < 4; ++mt)
#pragma unroll
                for (int nt = 0; nt < 4; ++nt) {
                    mma_tf32(acc[mt][nt], ah[mt], bh[nt]);
                    mma_tf32(acc[mt][nt], al[mt], bh[nt]);
                    mma_tf32(acc[mt][nt], ah[mt], bl[nt]);
                }
        }
        __syncthreads();
    }

#pragma unroll
    for (int mt = 0; mt < 4; ++mt) {
#pragma unroll
        for (int nt = 0; nt < 4; ++nt) {
#pragma unroll
            for (int v = 0; v < 4; ++v) {
                const int row = wm + mt * 16 + (lane >> 2) + (v >> 1) * 8;
                const int col = wn + nt * 8 + 2 * (lane & 3) + (v & 1);
                const int m = m0 + row;
                if (m >= NM) continue;
                const int n = n0 + col;
                const int bI = m / NS;
                const int sI = m - bI * NS;
                const int h = n >> 6, d = n & 63;
                out[(((size_t)bI * NHEADS + h) * NS + sI) * NDH + d] =
                    acc[mt][nt][v] + bias[n];
            }
        }
    }
}

// ---------------------------------------------------------------------------
// Kernel 2: attention with geometric bias — FUSED score pass (R2 + R11 hybrid).
// k-group-outer: warp owns 4 k's (kk=lane>>3, sub=lane&7, full-128B lines).
// K row loaded ONCE into registers, reused for all 14 queries.
// qi-inner unrolled x2 with 4 rpe LDG.128 front-batched (R11 duty-cycle fix).
// One shuffle chain covers q.K + g.rpe + mask -> single STS to sc (no RMW).
// Group 48 falls naturally on warp 0 (48 % 8 == 0).
// ---------------------------------------------------------------------------
#define TQ 14
#define SP 200
#define NG 49            // 196 / 4 k-groups

__device__ __forceinline__ float dot4(float4 a, float4 b) {
    return a.x * b.x + a.y * b.y + a.z * b.z + a.w * b.w;
}

__global__ __launch_bounds__(256, 5) void attn_kernel(
    const float* __restrict__ rpe, const float* __restrict__ mask,
    float* __restrict__ out_ctx, float* __restrict__ out_probs,
    int write_probs)
{
    __shared__ float qsm[TQ * NDH];    // pre-scaled q
    __shared__ float gsm[TQ * NDH];
    __shared__ float sc[TQ * SP];
    __shared__ float msk[NS];

    const int q0 = blockIdx.x * TQ;
    const int h  = blockIdx.y;
    const int b  = blockIdx.z;
    const int bh = b * NHEADS + h;
    const int tid  = threadIdx.x;
    const int warp = tid >> 5;
    const int lane = tid & 31;
    const int kk  = lane >> 3;   // 0..3: k-row within 4-group
    const int sub = lane & 7;    // 0..7: 16B segment within row

    // ---- stage q, g, mask ----
    {
        const float* Qb = g_Q + ((size_t)bh * NS + q0) * NDH;
        const float* Gb = g_G + ((size_t)bh * NS + q0) * NDH;
        for (int j = tid; j < TQ * NDH; j += 256) {
            qsm[j] = Qb[j] * 0.125f;   // 1/sqrt(64)
            gsm[j] = Gb[j];
        }
        if (tid < NS) msk[tid] = mask[b * NS + tid];
    }
    __syncthreads();

    // ---- fused score pass: sc = scale*q.K + g.rpe + mask ----
    const float* Kbh = g_K + (size_t)bh * NS * NDH;
    const float* rb  = rpe + ((size_t)bh * NS + q0) * (size_t)NS * NDH;

    for (int grp = warp; grp < NG; grp += 8) {
        const int k = grp * 4 + kk;          // < 196 always
        const float* krow = Kbh + (size_t)k * NDH;
        const float4 kv0 = *(const float4*)(krow + sub * 4);
        const float4 kv1 = *(const float4*)(krow + (sub + 8) * 4);
        const float mk = msk[k];
        const float* rk = rb + (size_t)k * NDH;

#pragma unroll 2
        for (int qi = 0; qi < TQ; qi += 2) {
            const float* p0 = rk + (size_t)qi * NS * NDH;
            const float* p1 = p0 + (size_t)NS * NDH;
            // 4 rpe LDG.128, front-batched
            const float4 ra0 = *(const float4*)(p0 + sub * 4);
            const float4 ra1 = *(const float4*)(p0 + (sub + 8) * 4);
            const float4 rb0 = *(const float4*)(p1 + sub * 4);
            const float4 rb1 = *(const float4*)(p1 + (sub + 8) * 4);

            const float4 qa0 = *(const float4*)&qsm[qi * NDH + sub * 4];
            const float4 qa1 = *(const float4*)&qsm[qi * NDH + (sub + 8) * 4];
            const float4 ga0 = *(const float4*)&gsm[qi * NDH + sub * 4];
            const float4 ga1 = *(const float4*)&gsm[qi * NDH + (sub + 8) * 4];
            const float4 qb0 = *(const float4*)&qsm[(qi + 1) * NDH + sub * 4];
            const float4 qb1 = *(const float4*)&qsm[(qi + 1) * NDH + (sub + 8) * 4];
            const float4 gb0 = *(const float4*)&gsm[(qi + 1) * NDH + sub * 4];
            const float4 gb1 = *(const float4*)&gsm[(qi + 1) * NDH + (sub + 8) * 4];

            float sA = dot4(qa0, kv0) + dot4(qa1, kv1)
                     + dot4(ga0, ra0) + dot4(ga1, ra1);
            float sB = dot4(qb0, kv0) + dot4(qb1, kv1)
                     + dot4(gb0, rb0) + dot4(gb1, rb1);

            sA += __shfl_xor_sync(0xffffffffu, sA, 1);
            sB += __shfl_xor_sync(0xffffffffu, sB, 1);
            sA += __shfl_xor_sync(0xffffffffu, sA, 2);
            sB += __shfl_xor_sync(0xffffffffu, sB, 2);
            sA += __shfl_xor_sync(0xffffffffu, sA, 4);
            sB += __shfl_xor_sync(0xffffffffu, sB, 4);
            if (sub == 0) {
                sc[qi * SP + k]       = sA + mk;
                sc[(qi + 1) * SP + k] = sB + mk;
            }
        }
    }
    __syncthreads();

    // ---- softmax per row + probs write ----
    for (int qi = warp; qi < TQ; qi += 8) {
        float m = -1e30f;
        for (int j = lane; j < NS; j += 32) m = fmaxf(m, sc[qi * SP + j]);
#pragma unroll
        for (int o = 16; o; o >>= 1) m = fmaxf(m, __shfl_xor_sync(0xffffffffu, m, o));
        float sum = 0.f;
        for (int j = lane; j < NS; j += 32) {
            const float e = __expf(sc[qi * SP + j] - m);
            sc[qi * SP + j] = e;
            sum += e;
        }
#pragma unroll
        for (int o = 16; o; o >>= 1) sum += __shfl_xor_sync(0xffffffffu, sum, o);
        const float inv = 1.0f / sum;
        const size_t pb = ((size_t)bh * NS + q0 + qi) * NS;
        for (int j = lane; j < NS; j += 32) {
            const float p = sc[qi * SP + j] * inv;
            sc[qi * SP + j] = p;
            if (write_probs) out_probs[pb + j] = p;
        }
    }
    __syncthreads();

    // ---- ctx = probs @ V ----
    const int g = tid >> 6;      // 0..3
    const int d = tid & 63;
    const int nq = (g < 2) ? 4 : 3;
    const float* Vb = g_V + (size_t)bh * NS * NDH;

    float acc[4] = {0.f, 0.f, 0.f, 0.f};
#pragma unroll 4
    for (int k = 0; k < NS; ++k) {
        const float v = Vb[(size_t)k * NDH + d];
#pragma unroll
        for (int t = 0; t < 4; ++t)
            if (t < nq) acc[t] += sc[(g + 4 * t) * SP + k] * v;
    }
#pragma unroll
    for (int t = 0; t < 4; ++t) {
        if (t >= nq) break;
        const int qi = g + 4 * t;
        out_ctx[(((size_t)b * NS + q0 + qi) * NHEADS + h) * NDH + d] = acc[t];
    }
}

// ---------------------------------------------------------------------------
extern "C" void kernel_launch(void* const* d_in, const int* in_sizes, int n_in,
                              void* d_out, int out_size)
{
    const float* hidden = (const float*)d_in[0];
    const float* rpe    = (const float*)d_in[1];
    const float* mask   = (const float*)d_in[2];
    const float* Wq = (const float*)d_in[3];
    const float* bq = (const float*)d_in[4];
    const float* Wk = (const float*)d_in[5];
    const float* bk = (const float*)d_in[6];
    const float* Wv = (const float*)d_in[7];
    const float* bv = (const float*)d_in[8];
    const float* Wg = (const float*)d_in[9];
    const float* bg = (const float*)d_in[10];

    float* out = (float*)d_out;
    const size_t ctx_elems   = (size_t)NB * NS * NHID;
    const size_t probs_elems = (size_t)NB * NHEADS * NS * NS;
    const int write_probs = ((size_t)out_size >= ctx_elems + probs_elems) ? 1 : 0;
    float* out_probs = out + ctx_elems;

    proj_kernel<<<dim3(4, 25, 4), 256>>>(hidden, Wq, bq, Wk, bk, Wv, bv, Wg, bg);
    attn_kernel<<<dim3(NS / TQ, NHEADS, NB), 256>>>(
        rpe, mask, out, out_probs, write_probs);
}